// round 10
// baseline (speedup 1.0000x reference)
#include <cuda_runtime.h>
#include <math.h>
#include <stdint.h>

// ---------------------------------------------------------------------------
// Weighted Kabsch, fused, deep TMA pipeline.
// Per CTA (one batch): FOUR tile buffers (= whole batch for N=2048). Thread 0
// posts all cp.async.bulk transfers up front; consumers wait per-tile on
// mbarriers (no per-tile __syncthreads, no buffer reuse on the hot shape).
// Block-reduce 16 sufficient statistics; thread 0 runs the fp32 3x3 SVD +
// rigid-transform epilogue.
// ---------------------------------------------------------------------------

#define THREADS 128
#define TILE 512                 // points per tile (4 per thread)
#define NBUF 4

struct __align__(16) Smem {
    float src[NBUF][TILE * 3];   // 24 KB
    float tgt[NBUF][TILE * 3];   // 24 KB
    float wgt[NBUF][TILE];       //  8 KB
    float red[THREADS / 32][16];
    unsigned long long mbar[NBUF];
};

__device__ __forceinline__ void mbar_init(uint32_t a, uint32_t cnt) {
    asm volatile("mbarrier.init.shared.b64 [%0], %1;" :: "r"(a), "r"(cnt) : "memory");
}
__device__ __forceinline__ void mbar_expect_tx(uint32_t a, uint32_t bytes) {
    asm volatile("mbarrier.arrive.expect_tx.shared.b64 _, [%0], %1;"
                 :: "r"(a), "r"(bytes) : "memory");
}
__device__ __forceinline__ void bulk_g2s(uint32_t sdst, const void* gsrc,
                                         uint32_t bytes, uint32_t mbar) {
    asm volatile(
        "cp.async.bulk.shared::cta.global.mbarrier::complete_tx::bytes [%0], [%1], %2, [%3];"
        :: "r"(sdst), "l"(gsrc), "r"(bytes), "r"(mbar) : "memory");
}
__device__ __forceinline__ void mbar_wait(uint32_t a, uint32_t parity) {
    uint32_t done;
    asm volatile(
        "{\n\t.reg .pred p;\n\t"
        "mbarrier.try_wait.parity.acquire.cta.shared::cta.b64 p, [%1], %2;\n\t"
        "selp.b32 %0, 1, 0, p;\n\t}"
        : "=r"(done) : "r"(a), "r"(parity) : "memory");
    if (!done) {
        asm volatile(
            "{\n\t.reg .pred P1;\n\t"
            "WL_%=:\n\t"
            "mbarrier.try_wait.parity.acquire.cta.shared::cta.b64 P1, [%0], %1, 0x989680;\n\t"
            "@P1 bra.uni WD_%=;\n\t"
            "bra.uni WL_%=;\n\t"
            "WD_%=:\n\t}"
            :: "r"(a), "r"(parity) : "memory");
    }
}

__device__ __forceinline__ float det3f(const float m[3][3]) {
    return m[0][0] * (m[1][1] * m[2][2] - m[1][2] * m[2][1])
         - m[0][1] * (m[1][0] * m[2][2] - m[1][2] * m[2][0])
         + m[0][2] * (m[1][0] * m[2][1] - m[1][1] * m[2][0]);
}

__global__ void __launch_bounds__(THREADS)
kabsch_kernel(const float* __restrict__ src,
              const float* __restrict__ tgt,
              const float* __restrict__ wts,
              float* __restrict__ out,
              int N, int B)
{
    extern __shared__ char smem_raw[];
    Smem& sm = *(Smem*)smem_raw;

    const int b = blockIdx.x;
    const int tid = threadIdx.x;
    const char* gS = (const char*)(src + (size_t)b * N * 3);
    const char* gT = (const char*)(tgt + (size_t)b * N * 3);
    const char* gW = (const char*)(wts + (size_t)b * N);

    const int ntiles = (N + TILE - 1) / TILE;

    uint32_t mb[NBUF], sS[NBUF], sT[NBUF], sW[NBUF];
#pragma unroll
    for (int i = 0; i < NBUF; i++) {
        mb[i] = (uint32_t)__cvta_generic_to_shared(&sm.mbar[i]);
        sS[i] = (uint32_t)__cvta_generic_to_shared(&sm.src[i][0]);
        sT[i] = (uint32_t)__cvta_generic_to_shared(&sm.tgt[i][0]);
        sW[i] = (uint32_t)__cvta_generic_to_shared(&sm.wgt[i][0]);
    }

    if (tid == 0) {
#pragma unroll
        for (int i = 0; i < NBUF; i++) mbar_init(mb[i], 1);
    }
    __syncthreads();

    auto stage = [&](int t) {
        const int bf = t & (NBUF - 1);
        const int npts = min(TILE, N - t * TILE);
        const uint32_t cbytes = (uint32_t)npts * 12u;
        const uint32_t wbytes = (uint32_t)npts * 4u;
        mbar_expect_tx(mb[bf], 2u * cbytes + wbytes);
        bulk_g2s(sS[bf], gS + (size_t)t * TILE * 12, cbytes, mb[bf]);
        bulk_g2s(sT[bf], gT + (size_t)t * TILE * 12, cbytes, mb[bf]);
        bulk_g2s(sW[bf], gW + (size_t)t * TILE * 4,  wbytes, mb[bf]);
    };

    // post the whole pipeline up front (covers the entire batch when
    // ntiles <= NBUF, which is the hot shape N=2048)
    if (tid == 0) {
        const int npre = min(ntiles, NBUF);
        for (int t = 0; t < npre; t++) stage(t);
    }

    float acc[16];
#pragma unroll
    for (int i = 0; i < 16; i++) acc[i] = 0.f;

    for (int t = 0; t < ntiles; t++) {
        const int bf = t & (NBUF - 1);
        mbar_wait(mb[bf], (uint32_t)(t / NBUF) & 1u);

        const int npts = min(TILE, N - t * TILE);
        const float4* Sf4 = (const float4*)sm.src[bf];
        const float4* Tf4 = (const float4*)sm.tgt[bf];
        const float4* Wf4 = (const float4*)sm.wgt[bf];

        // thread handles points 4*tid .. 4*tid+3
        if (tid * 4 < npts) {
            float4 wv = Wf4[tid];
            float4 a0 = Sf4[tid * 3 + 0];
            float4 a1 = Sf4[tid * 3 + 1];
            float4 a2 = Sf4[tid * 3 + 2];
            float4 b0 = Tf4[tid * 3 + 0];
            float4 b1 = Tf4[tid * 3 + 1];
            float4 b2 = Tf4[tid * 3 + 2];

            const float sx[4][3] = {{a0.x, a0.y, a0.z},
                                    {a0.w, a1.x, a1.y},
                                    {a1.z, a1.w, a2.x},
                                    {a2.y, a2.z, a2.w}};
            const float tx[4][3] = {{b0.x, b0.y, b0.z},
                                    {b0.w, b1.x, b1.y},
                                    {b1.z, b1.w, b2.x},
                                    {b2.y, b2.z, b2.w}};
            const float wa[4] = {wv.x, wv.y, wv.z, wv.w};

#pragma unroll
            for (int p = 0; p < 4; p++) {
                const float w = wa[p];
                const float s0 = sx[p][0], s1 = sx[p][1], s2 = sx[p][2];
                const float wt0 = w * tx[p][0];
                const float wt1 = w * tx[p][1];
                const float wt2 = w * tx[p][2];
                acc[0] += w;
                acc[1] += w * s0;  acc[2] += w * s1;  acc[3] += w * s2;
                acc[4] += wt0;     acc[5] += wt1;     acc[6] += wt2;
                acc[7]  += wt0 * s0;  acc[8]  += wt0 * s1;  acc[9]  += wt0 * s2;
                acc[10] += wt1 * s0;  acc[11] += wt1 * s1;  acc[12] += wt1 * s2;
                acc[13] += wt2 * s0;  acc[14] += wt2 * s1;  acc[15] += wt2 * s2;
            }
        }

        // buffer reuse only when ntiles > NBUF (not the hot shape)
        if (t + NBUF < ntiles) {
            __syncthreads();
            if (tid == 0) stage(t + NBUF);
        }
    }

    // warp reduce
#pragma unroll
    for (int i = 0; i < 16; i++) {
#pragma unroll
        for (int o = 16; o > 0; o >>= 1)
            acc[i] += __shfl_down_sync(0xffffffffu, acc[i], o);
    }

    const int warp = tid >> 5;
    const int lane = tid & 31;
    if (lane == 0) {
#pragma unroll
        for (int i = 0; i < 16; i++) sm.red[warp][i] = acc[i];
    }
    __syncthreads();

    if (tid != 0) return;

    // ---- thread 0: finalize stats, fast fp32 3x3 SVD + epilogue ----
    float s[16];
#pragma unroll
    for (int i = 0; i < 16; i++) {
        float v = sm.red[0][i];
#pragma unroll
        for (int w = 1; w < THREADS / 32; w++) v += sm.red[w][i];
        s[i] = v;
    }

    const float Sw = s[0];
    const float Sx[3] = {s[1], s[2], s[3]};
    const float Tx[3] = {s[4], s[5], s[6]};
    const float M[3][3] = {{s[7], s[8], s[9]},
                           {s[10], s[11], s[12]},
                           {s[13], s[14], s[15]}};

    const float w = Sw + 1e-4f;
    const float winv = __fdividef(1.0f, w);
    float sc[3], tc[3];
#pragma unroll
    for (int i = 0; i < 3; i++) { sc[i] = Sx[i] * winv; tc[i] = Tx[i] * winv; }

    float A[3][3];
#pragma unroll
    for (int i = 0; i < 3; i++)
#pragma unroll
        for (int j = 0; j < 3; j++)
            A[i][j] = (M[i][j] - tc[i] * Sx[j] - Tx[i] * sc[j] + Sw * tc[i] * sc[j]) * winv;

    float Bm[3][3];
#pragma unroll
    for (int i = 0; i < 3; i++)
#pragma unroll
        for (int j = 0; j < 3; j++)
            Bm[i][j] = A[0][i] * A[0][j] + A[1][i] * A[1][j] + A[2][i] * A[2][j];

    float V[3][3] = {{1, 0, 0}, {0, 1, 0}, {0, 0, 1}};

    // cyclic Jacobi, 5 sweeps, fast divides, convergence skip
#pragma unroll 1
    for (int sweep = 0; sweep < 5; sweep++) {
#pragma unroll
        for (int pair = 0; pair < 3; pair++) {
            const int p = (pair == 2) ? 1 : 0;
            const int q = (pair == 0) ? 1 : 2;
            const float apq = Bm[p][q];
            const float app = Bm[p][p], aqq = Bm[q][q];
            if (apq * apq <= 1e-22f * app * aqq + 1e-38f) continue;
            const float tau = __fdividef(aqq - app, 2.0f * apq);
            const float t = __fdividef((tau >= 0.0f) ? 1.0f : -1.0f,
                                       fabsf(tau) + sqrtf(1.0f + tau * tau));
            const float c = rsqrtf(1.0f + t * t);
            const float sn = t * c;
#pragma unroll
            for (int k = 0; k < 3; k++) {
                const float bkp = Bm[k][p], bkq = Bm[k][q];
                Bm[k][p] = c * bkp - sn * bkq;
                Bm[k][q] = sn * bkp + c * bkq;
            }
#pragma unroll
            for (int k = 0; k < 3; k++) {
                const float bpk = Bm[p][k], bqk = Bm[q][k];
                Bm[p][k] = c * bpk - sn * bqk;
                Bm[q][k] = sn * bpk + c * bqk;
            }
#pragma unroll
            for (int k = 0; k < 3; k++) {
                const float vkp = V[k][p], vkq = V[k][q];
                V[k][p] = c * vkp - sn * vkq;
                V[k][q] = sn * vkp + c * vkq;
            }
        }
    }

    float lam[3] = {Bm[0][0], Bm[1][1], Bm[2][2]};
#pragma unroll
    for (int i = 0; i < 2; i++)
#pragma unroll
        for (int j = 0; j < 2 - i; j++)
            if (lam[j] < lam[j + 1]) {
                float tl = lam[j]; lam[j] = lam[j + 1]; lam[j + 1] = tl;
#pragma unroll
                for (int k = 0; k < 3; k++) {
                    float tv = V[k][j]; V[k][j] = V[k][j + 1]; V[k][j + 1] = tv;
                }
            }

    float U[3][3];
    float norms[3];
#pragma unroll
    for (int k = 0; k < 3; k++) {
        float uv[3];
#pragma unroll
        for (int i = 0; i < 3; i++)
            uv[i] = A[i][0] * V[0][k] + A[i][1] * V[1][k] + A[i][2] * V[2][k];
        const float nsq = uv[0] * uv[0] + uv[1] * uv[1] + uv[2] * uv[2];
        norms[k] = sqrtf(nsq);
        const float inv = (nsq > 1e-36f) ? rsqrtf(nsq) : 0.0f;
#pragma unroll
        for (int i = 0; i < 3; i++) U[i][k] = uv[i] * inv;
    }
    if (norms[2] < 1e-7f * (norms[0] + 1e-30f)) {
        U[0][2] = U[1][0] * U[2][1] - U[2][0] * U[1][1];
        U[1][2] = U[2][0] * U[0][1] - U[0][0] * U[2][1];
        U[2][2] = U[0][0] * U[1][1] - U[1][0] * U[0][1];
    }

    const float d = det3f(U) * det3f(V);

    float R[3][3];
#pragma unroll
    for (int i = 0; i < 3; i++)
#pragma unroll
        for (int j = 0; j < 3; j++)
            R[i][j] = U[i][0] * V[j][0] + U[i][1] * V[j][1] + d * U[i][2] * V[j][2];

    float t1[3], t[3];
#pragma unroll
    for (int i = 0; i < 3; i++)
        t1[i] = sc[i] - (R[0][i] * tc[0] + R[1][i] * tc[1] + R[2][i] * tc[2]);
#pragma unroll
    for (int i = 0; i < 3; i++)
        t[i] = -(R[i][0] * t1[0] + R[i][1] * t1[1] + R[i][2] * t1[2]);

    float* Rout = out + (size_t)b * 9;
    float* Tout = out + (size_t)B * 9 + (size_t)b * 3;
#pragma unroll
    for (int i = 0; i < 3; i++)
#pragma unroll
        for (int j = 0; j < 3; j++)
            Rout[i * 3 + j] = R[i][j];
#pragma unroll
    for (int i = 0; i < 3; i++) Tout[i] = t[i];
}

// ---------------------------------------------------------------------------

extern "C" void kernel_launch(void* const* d_in, const int* in_sizes, int n_in,
                              void* d_out, int out_size)
{
    const float* src = (const float*)d_in[0];
    const float* tgt = (const float*)d_in[1];
    const float* wts = (const float*)d_in[2];
    float* out = (float*)d_out;

    const int B = out_size / 12;            // 9 (R) + 3 (t) per batch
    const int N = in_sizes[2] / B;          // weights are (B,1,N)

    static bool attr_set = false;
    if (!attr_set) {
        cudaFuncSetAttribute(kabsch_kernel,
                             cudaFuncAttributeMaxDynamicSharedMemorySize,
                             (int)sizeof(Smem));
        attr_set = true;
    }

    kabsch_kernel<<<B, THREADS, sizeof(Smem)>>>(src, tgt, wts, out, N, B);
}